// round 6
// baseline (speedup 1.0000x reference)
#include <cuda_runtime.h>
#include <cstdint>

constexpr int B = 64;
constexpr int T = 1024;
constexpr int V = 512;
constexpr int L = 128;
constexpr int NSTAGE = 12;       // cp.async row ring depth (24 KB)
constexpr int THREADS = 128;     // 4 warps; lane l of warp w owns states 64w+2l, 64w+2l+1
constexpr int K = 4;             // recursion steps per __syncthreads window
constexpr int NWIN = 256;        // K*NWIN = 1024 steps (t=1..1024; step 1024 is harmless garbage)

#define NEG2   (-1.44269504e30f)     // -1e30 in log2 domain
#define LOG2E  1.4426950408889634f
#define LN2    0.6931471805599453f
#define FULLM  0xffffffffu

__device__ float g_loss[B];
__device__ int   g_ctr = 0;

__device__ __forceinline__ float ex2f(float x) {
    float y; asm("ex2.approx.f32 %0, %1;" : "=f"(y) : "f"(x)); return y;
}
__device__ __forceinline__ float lg2f(float x) {
    float y; asm("lg2.approx.f32 %0, %1;" : "=f"(y) : "f"(x)); return y;
}
// 2-way logsumexp in log2 domain: 2 MUFU via min/max form
__device__ __forceinline__ float lse2(float a, float b) {
    const float m  = fmaxf(a, b);
    const float mn = fminf(a, b);
    return m + lg2f(1.0f + ex2f(mn - m));
}
__device__ __forceinline__ float lse3(float a, float b, float c) {
    const float m = fmaxf(a, fmaxf(b, c));
    return m + lg2f(ex2f(a - m) + ex2f(b - m) + ex2f(c - m));
}

__device__ __forceinline__ void cp_async16(void* sptr, const void* gptr) {
    uint32_t sa = (uint32_t)__cvta_generic_to_shared(sptr);
    asm volatile("cp.async.cg.shared.global [%0], [%1], 16;\n" ::"r"(sa), "l"(gptr));
}
__device__ __forceinline__ void cp_commit() {
    asm volatile("cp.async.commit_group;\n");
}
template <int N>
__device__ __forceinline__ void cp_wait() {
    asm volatile("cp.async.wait_group %0;\n" ::"n"(N));
}

__global__ __launch_bounds__(THREADS, 1)
void ctc_fused_kernel(const float* __restrict__ outputs,
                      const int*   __restrict__ labels,
                      const int*   __restrict__ output_lengths,
                      const int*   __restrict__ label_lengths,
                      float* __restrict__ out) {
    __shared__ __align__(16) float rowbuf[NSTAGE][V];   // 24 KB
    __shared__ float bnd[2][4][8];   // [buf][warp][0..3=A, 4..7=B] of lanes 28..31
    __shared__ float fin[2];

    const int b    = blockIdx.x;
    const int tid  = threadIdx.x;
    const int lane = tid & 31;
    const int w    = tid >> 5;

    const int olen = output_lengths[b];
    const int llen = label_lengths[b];
    const int tcap = olen - 1;
    const int s0g  = 2 * llen - 1;       // odd
    const int s1g  = 2 * llen;           // even (or 256)

    const int sA = (w << 6) + (lane << 1);   // even state
    const int sB = sA + 1;                   // odd state; label index = tid

    // static per-thread data
    const int* lb = labels + b * L;
    const int  colB  = __ldg(lb + tid);
    const bool skipB = (tid > 0) && (colB != __ldg(lb + tid - 1));

    // halo label data: halo lane l (28..31) of warp w mirrors label index 32(w-1)+l
    int  colBh  = 0;
    bool skipBh = false;
    if (w > 0 && lane >= 28) {
        const int lih = 32 * (w - 1) + lane;
        colBh  = __ldg(lb + lih);
        skipBh = (colBh != __ldg(lb + lih - 1));
    }

    const bool capA1 = (sA == s1g);
    const bool capB0 = (sB == s0g);
    const bool capC1 = (tid == 127) && (s1g == 256);
    const bool haloRd = (w > 0) && (lane >= 28);
    const bool haloWr = (lane >= 28);

    // ---- cp.async prologue: rows 0..7 ----
    const float* gb = outputs + (size_t)b * T * V;
    const int le = tid * 4;
    #pragma unroll
    for (int k = 0; k < 8; ++k) {
        cp_async16(&rowbuf[k][le], gb + (size_t)k * V + le);
        cp_commit();
    }

    cp_wait<7>();     // row 0 landed
    __syncthreads();

    // ---- peeled t = 0 ----
    float A, Bv, C = NEG2;
    float cap0 = NEG2, cap1 = NEG2;
    {
        const float* r0 = rowbuf[0];
        A  = (sA == 0) ? r0[0]    * LOG2E : NEG2;
        Bv = (sB == 1) ? r0[colB] * LOG2E : NEG2;
        const bool pc = (tcap == 0);
        cap1 = (pc && capA1) ? A  : cap1;
        cap0 = (pc && capB0) ? Bv : cap0;
        if (haloWr) { bnd[0][w][lane - 28] = A; bnd[0][w][4 + lane - 28] = Bv; }
    }

    int rslot = 1;     // SMEM slot of row t0 = 4*win+1
    int wrow  = 8;     // next global row index to issue
    int wslot = 8;     // its slot
    int p     = 0;     // boundary buffer to read this window

    // ---- main recursion: 256 windows of 4 steps, one barrier each ----
    for (int win = 0; win < NWIN; ++win) {
        cp_wait<3>();        // rows <= 4*win+4 landed
        __syncthreads();     // + previous window's boundary publish visible

        // halo init from warp w-1's window-start boundary
        float hA = NEG2, hB = NEG2;
        if (haloRd) {
            hA = bnd[p][w - 1][lane - 28];
            hB = bnd[p][w - 1][4 + lane - 28];
        }

        // prefetch all emits for the 4 steps (off the dependency chain)
        float eAv[K], eBv[K], eHv[K];
        #pragma unroll
        for (int j = 0; j < K; ++j) {
            int sj = rslot + j; sj -= (sj >= NSTAGE) ? NSTAGE : 0;
            const float* rp = rowbuf[sj];
            eAv[j] = rp[0]     * LOG2E;
            eBv[j] = rp[colB]  * LOG2E;
            eHv[j] = rp[colBh] * LOG2E;
        }

        // issue the next 4 rows (clamped gmem address, unclamped slot)
        #pragma unroll
        for (int k = 0; k < K; ++k) {
            const int u  = wrow + k;
            const int cu = (u < T) ? u : (T - 1);
            int ws = wslot + k; ws -= (ws >= NSTAGE) ? NSTAGE : 0;
            cp_async16(&rowbuf[ws][le], gb + (size_t)cu * V + le);
            cp_commit();
        }
        wrow += K;
        wslot += K; wslot -= (wslot >= NSTAGE) ? NSTAGE : 0;

        const int t0 = (win << 2) + 1;
        #pragma unroll
        for (int j = 0; j < K; ++j) {
            // single rotated shuffle shifts the halo AND feeds lane 0's boundary
            const float hBr = __shfl_sync(FULLM, hB, (lane + 31) & 31);
            float Bm1 = __shfl_up_sync(FULLM, Bv, 1);
            Bm1 = (lane == 0) ? hBr : Bm1;

            const float nC  = lse2(C, Bv) + eAv[j];          // state 256 (tid 127)
            const float nA  = lse2(A, Bm1) + eAv[j];
            const float nB  = lse3(Bv, A, skipB ? Bm1 : NEG2) + eBv[j];
            const float nhA = lse2(hA, hBr) + eAv[j];
            const float nhB = lse3(hB, hA, skipBh ? hBr : NEG2) + eHv[j];
            A = nA; Bv = nB; C = nC; hA = nhA; hB = nhB;

            const bool pc = ((t0 + j) == tcap);
            cap1 = (pc && capA1) ? A  : cap1;
            cap0 = (pc && capB0) ? Bv : cap0;
            cap1 = (pc && capC1) ? C  : cap1;
        }

        // publish window-end boundary (lanes 28..31)
        if (haloWr) {
            bnd[p ^ 1][w][lane - 28]     = A;
            bnd[p ^ 1][w][4 + lane - 28] = Bv;
        }
        p ^= 1;
        rslot += K; rslot -= (rslot >= NSTAGE) ? NSTAGE : 0;
    }

    // ---- finish ----
    __syncthreads();
    if (capB0) fin[0] = cap0;
    if (capA1 || capC1) fin[1] = cap1;
    __syncthreads();

    if (tid == 0) {
        const float ll = lse2(fin[0], fin[1]) * LN2;
        g_loss[b] = -ll / (float)llen;
        __threadfence();
        const int old = atomicAdd(&g_ctr, 1);
        if (old == B - 1) {
            __threadfence();
            float s = 0.0f;
            #pragma unroll 8
            for (int i = 0; i < B; ++i) s += g_loss[i];
            *out = s * (1.0f / (float)B);
            g_ctr = 0;   // reset for next graph replay
        }
    }
}

extern "C" void kernel_launch(void* const* d_in, const int* in_sizes, int n_in,
                              void* d_out, int out_size) {
    const float* outputs        = (const float*)d_in[0];
    const int*   labels         = (const int*)d_in[1];
    const int*   output_lengths = (const int*)d_in[2];
    const int*   label_lengths  = (const int*)d_in[3];
    float* out = (float*)d_out;

    ctc_fused_kernel<<<B, THREADS>>>(outputs, labels, output_lengths,
                                     label_lengths, out);
}